// round 15
// baseline (speedup 1.0000x reference)
#include <cuda_runtime.h>
#include <cstdint>

#define N_NODES_C 100000
#define N_EDGES_C 1600000
#define D_FEAT 64
#define D_VEC  (D_FEAT / 4)
#define CAP 64            // per-node bucket capacity (Poisson(16): P(>64) ~ 1e-20)
#define OVF_CAP 8192
#define WEIGHT 0.15f
#define BATCH 4           // nodes grabbed per warp per ticket

// packed f32x2 add (Blackwell): one instruction adds two floats in a 64b pair
#define ADD_F32X2(out, a, b) \
    asm("add.rn.f32x2 %0, %1, %2;" : "=l"(out) : "l"(a), "l"(b))

// -------------------- device scratch (static, zero-initialized) ------------
// Invariants (hold at entry of every kernel_launch, for this fixed input):
//  * g_count[] zero (zero-init call 1; aggregate resets per node).
//  * g_ticket, g_bar, g_bar2 zero (zero-init call 1; epilogue resets).
//  * bucket slots [deg(node), CAP) NEVER written -> stay zero forever, so
//    early reads are safe. Entries are PRE-SCALED BYTE OFFSETS (src * 256).
__device__ unsigned int g_bucket[(size_t)N_NODES_C * CAP];
__device__ int g_count[N_NODES_C];
__device__ int g_ovf_edges[OVF_CAP];
__device__ int g_ovf_count;
__device__ int g_ticket;
__device__ unsigned int g_bar;
__device__ unsigned int g_bar2;

// -------------------- per-node aggregation body (R12/R13, proven) -----------
__device__ __forceinline__ void aggregate_one_node(
    int node, int lane,
    const unsigned long long* __restrict__ x2u,
    float2* __restrict__ out2,
    const int* __restrict__ ei) {

    const unsigned int* b = &g_bucket[(size_t)node * CAP];
    const char* xb = reinterpret_cast<const char*>(x2u) + lane * 8;

    // concurrent prologue loads (independent)
    uint4 s0 = *reinterpret_cast<const uint4*>(b);
    uint4 s1 = *reinterpret_cast<const uint4*>(b + 4);
    int deg = g_count[node];
    unsigned long long xv = __ldg(&x2u[(size_t)node * 32 + lane]);

    int degc = deg > CAP ? CAP : deg;
    unsigned long long acc = 0ull;

    if (degc > 0) {
        int j = 0;
        while (true) {
            uint4 c0 = s0, c1 = s1;
            int next = j + 8;
            if (next < degc) {
                s0 = *reinterpret_cast<const uint4*>(b + next);
                s1 = *reinterpret_cast<const uint4*>(b + next + 4);
            }
            if (next <= degc) {
                unsigned long long u0 = __ldg((const unsigned long long*)(xb + c0.x));
                unsigned long long u1 = __ldg((const unsigned long long*)(xb + c0.y));
                unsigned long long u2 = __ldg((const unsigned long long*)(xb + c0.z));
                unsigned long long u3 = __ldg((const unsigned long long*)(xb + c0.w));
                unsigned long long u4 = __ldg((const unsigned long long*)(xb + c1.x));
                unsigned long long u5 = __ldg((const unsigned long long*)(xb + c1.y));
                unsigned long long u6 = __ldg((const unsigned long long*)(xb + c1.z));
                unsigned long long u7 = __ldg((const unsigned long long*)(xb + c1.w));
                unsigned long long t01, t23, t45, t67, t03, t47, t07;
                ADD_F32X2(t01, u0, u1);
                ADD_F32X2(t23, u2, u3);
                ADD_F32X2(t45, u4, u5);
                ADD_F32X2(t67, u6, u7);
                ADD_F32X2(t03, t01, t23);
                ADD_F32X2(t47, t45, t67);
                ADD_F32X2(t07, t03, t47);
                ADD_F32X2(acc, acc, t07);
            } else {
                int rem = degc - j;                     // 1..7
                unsigned int offs[8] = { c0.x, c0.y, c0.z, c0.w,
                                         c1.x, c1.y, c1.z, c1.w };
                unsigned long long u[8];
                #pragma unroll
                for (int k = 0; k < 8; k++) {
                    if (k < rem) u[k] = __ldg((const unsigned long long*)(xb + offs[k]));
                    else         u[k] = 0ull;
                }
                unsigned long long t01, t23, t45, t67, t03, t47, t07;
                ADD_F32X2(t01, u[0], u[1]);
                ADD_F32X2(t23, u[2], u[3]);
                ADD_F32X2(t45, u[4], u[5]);
                ADD_F32X2(t67, u[6], u[7]);
                ADD_F32X2(t03, t01, t23);
                ADD_F32X2(t47, t45, t67);
                ADD_F32X2(t07, t03, t47);
                ADD_F32X2(acc, acc, t07);
            }
            j = next;
            if (j >= degc) break;
        }
    }

    float2 accf;
    accf.x = __uint_as_float((unsigned)(acc & 0xffffffffull));
    accf.y = __uint_as_float((unsigned)(acc >> 32));

    int ovf = g_ovf_count;
    if (ovf > 0) {
        if (ovf > OVF_CAP) ovf = OVF_CAP;
        for (int k = 0; k < ovf; k++) {
            int e = g_ovf_edges[k];
            if (__ldg(&ei[N_EDGES_C + e]) == node) {
                int s = __ldg(&ei[e]);
                unsigned long long uu = __ldg(&x2u[(size_t)s * 32 + lane]);
                accf.x += __uint_as_float((unsigned)(uu & 0xffffffffull));
                accf.y += __uint_as_float((unsigned)(uu >> 32));
            }
        }
    }

    float2 xvf;
    xvf.x = __uint_as_float((unsigned)(xv & 0xffffffffull));
    xvf.y = __uint_as_float((unsigned)(xv >> 32));

    float2 o;
    o.x = fmaf(WEIGHT, accf.x, xvf.x);
    o.y = fmaf(WEIGHT, accf.y, xvf.y);
    out2[(size_t)node * 32 + lane] = o;

    if (lane == 0) g_count[node] = 0;   // consume-and-reset
}

// -------------------- fused fill + barrier + aggregate ----------------------
// All blocks are resident (grid = SMs * 6, occupancy forced by launch bounds),
// so the software grid barrier cannot deadlock.
__global__ void __launch_bounds__(256, 6)
appr_fused_kernel(const int* __restrict__ ei,
                  const unsigned long long* __restrict__ x2u,
                  float2* __restrict__ out2) {
    int t = blockIdx.x * blockDim.x + threadIdx.x;
    int nthreads = gridDim.x * blockDim.x;
    int lane = threadIdx.x & 31;

    // ---------------- phase 1: bucket fill (4-edge quads, grid-stride) ------
    int nquads = N_EDGES_C / 4;
    for (int q = t; q < nquads; q += nthreads) {
        int e0 = q * 4;
        int4 src = *reinterpret_cast<const int4*>(ei + e0);
        int4 dst = *reinterpret_cast<const int4*>(ei + N_EDGES_C + e0);

        int p0 = atomicAdd(&g_count[dst.x], 1);
        int p1 = atomicAdd(&g_count[dst.y], 1);
        int p2 = atomicAdd(&g_count[dst.z], 1);
        int p3 = atomicAdd(&g_count[dst.w], 1);

        if (p0 < CAP) g_bucket[(size_t)dst.x * CAP + p0] = (unsigned)src.x << 8;
        else { int o = atomicAdd(&g_ovf_count, 1); if (o < OVF_CAP) g_ovf_edges[o] = e0; }
        if (p1 < CAP) g_bucket[(size_t)dst.y * CAP + p1] = (unsigned)src.y << 8;
        else { int o = atomicAdd(&g_ovf_count, 1); if (o < OVF_CAP) g_ovf_edges[o] = e0 + 1; }
        if (p2 < CAP) g_bucket[(size_t)dst.z * CAP + p2] = (unsigned)src.z << 8;
        else { int o = atomicAdd(&g_ovf_count, 1); if (o < OVF_CAP) g_ovf_edges[o] = e0 + 2; }
        if (p3 < CAP) g_bucket[(size_t)dst.w * CAP + p3] = (unsigned)src.w << 8;
        else { int o = atomicAdd(&g_ovf_count, 1); if (o < OVF_CAP) g_ovf_edges[o] = e0 + 3; }
    }

    // ---------------- software grid barrier ---------------------------------
    __syncthreads();
    if (threadIdx.x == 0) {
        __threadfence();                       // release phase-1 writes
        atomicAdd(&g_bar, 1u);
        while (true) {
            unsigned int v = *((volatile unsigned int*)&g_bar);
            if (v >= gridDim.x) break;
            __nanosleep(64);
        }
        __threadfence();                       // acquire
    }
    __syncthreads();

    // ---------------- phase 2: ticket-based aggregate -----------------------
    while (true) {
        int base = 0;
        if (lane == 0) base = atomicAdd(&g_ticket, BATCH);
        base = __shfl_sync(0xffffffffu, base, 0);
        if (base >= N_NODES_C) break;
        int end = base + BATCH;
        if (end > N_NODES_C) end = N_NODES_C;
        for (int node = base; node < end; node++) {
            aggregate_one_node(node, lane, x2u, out2, ei);
        }
    }

    // ---------------- epilogue: last block resets barrier/ticket state ------
    __syncthreads();
    if (threadIdx.x == 0) {
        __threadfence();
        unsigned int d = atomicAdd(&g_bar2, 1u);
        if (d == gridDim.x - 1) {
            g_bar = 0;
            g_bar2 = 0;
            g_ticket = 0;
            g_ovf_count = g_ovf_count > 0 ? 0 : 0;   // reset (normally already 0)
        }
    }
}

// -------------------- fallback path (unexpected shapes) --------------------
__global__ void appr_copy_kernel(const float4* __restrict__ x4,
                                 float4* __restrict__ out4, long long n_vec) {
    long long i = (long long)blockIdx.x * blockDim.x + threadIdx.x;
    long long stride = (long long)gridDim.x * blockDim.x;
    for (; i < n_vec; i += stride) out4[i] = x4[i];
}

__global__ void appr_scatter_kernel(const float4* __restrict__ x4,
                                    const int* __restrict__ edge_index,
                                    float* __restrict__ out, long long n_edges) {
    long long t = (long long)blockIdx.x * blockDim.x + threadIdx.x;
    long long edge = t >> 4;
    int c = (int)(t & 15);
    if (edge >= n_edges) return;
    int src = __ldg(&edge_index[edge]);
    int dst = __ldg(&edge_index[n_edges + edge]);
    float4 v = __ldg(&x4[(long long)src * D_VEC + c]);
    v.x *= WEIGHT; v.y *= WEIGHT; v.z *= WEIGHT; v.w *= WEIGHT;
    float* p = out + (long long)dst * D_FEAT + c * 4;
    asm volatile("red.global.add.v4.f32 [%0], {%1, %2, %3, %4};"
                 :: "l"(p), "f"(v.x), "f"(v.y), "f"(v.z), "f"(v.w)
                 : "memory");
}

// ---------------------------------------------------------------------------
extern "C" void kernel_launch(void* const* d_in, const int* in_sizes, int n_in,
                              void* d_out, int out_size) {
    const float* x = (const float*)d_in[0];
    const int* edge_index = (const int*)d_in[1];
    float* out = (float*)d_out;

    long long n_x = in_sizes[0];
    long long n_edges = in_sizes[1] / 2;
    long long n_nodes = n_x / D_FEAT;

    if (n_nodes == N_NODES_C && n_edges == N_EDGES_C) {
        // grid = SMs * 6 so ALL blocks are resident (barrier is deadlock-free).
        int sms = 0;
        cudaDeviceGetAttribute(&sms, cudaDevAttrMultiProcessorCount, 0);
        if (sms <= 0) sms = 148;   // conservative floor (B300 die)
        int blocks = sms * 6;
        appr_fused_kernel<<<blocks, 256>>>(
            edge_index, (const unsigned long long*)x, (float2*)out);
    } else {
        // fallback: copy + RED scatter (touches no persistent state)
        long long n_vec = n_x / 4;
        int blocks = (int)((n_vec + 255) / 256);
        if (blocks > 8192) blocks = 8192;
        appr_copy_kernel<<<blocks, 256>>>((const float4*)x, (float4*)out, n_vec);
        long long total_threads = n_edges * 16;
        appr_scatter_kernel<<<(unsigned)((total_threads + 255) / 256), 256>>>(
            (const float4*)x, edge_index, out, n_edges);
    }
}

// round 16
// speedup vs baseline: 1.1289x; 1.1289x over previous
#include <cuda_runtime.h>
#include <cstdint>

#define N_NODES_C 100000
#define N_EDGES_C 1600000
#define D_FEAT 64
#define D_VEC  (D_FEAT / 4)
#define CAP 64            // per-node bucket capacity (Poisson(16): P(>64) ~ 1e-20)
#define OVF_CAP 8192
#define WEIGHT 0.15f
#define AGG_BLOCKS 912    // ~6 blocks/SM
#define BATCH 8           // nodes grabbed per warp per ticket (halves ticket atomics)

// packed f32x2 add (Blackwell): one instruction adds two floats in a 64b pair
#define ADD_F32X2(out, a, b) \
    asm("add.rn.f32x2 %0, %1, %2;" : "=l"(out) : "l"(a), "l"(b))

// -------------------- device scratch (static, zero-initialized) ------------
// Invariants (hold at entry of every kernel_launch, for this fixed input):
//  * g_count[] zero (zero-init call 1; aggregate resets per node).
//  * g_ticket zero at aggregate start (fill resets it each call, stream order).
//  * bucket slots [deg(node), CAP) NEVER written -> stay zero forever, so
//    early reads are safe. Entries are PRE-SCALED BYTE OFFSETS (src * 256).
__device__ unsigned int g_bucket[(size_t)N_NODES_C * CAP];
__device__ int g_count[N_NODES_C];
__device__ int g_ovf_edges[OVF_CAP];
__device__ int g_ovf_count;
__device__ int g_ticket;

// -------------------- 1) bucket fill (4 edges per thread) ------------------
__global__ void appr_fill_kernel(const int* __restrict__ ei) {
    int t = blockIdx.x * blockDim.x + threadIdx.x;
    if (t == 0) g_ticket = 0;            // reset node ticket for aggregate
    int e0 = t * 4;
    if (e0 >= N_EDGES_C) return;

    int4 src = *reinterpret_cast<const int4*>(ei + e0);
    int4 dst = *reinterpret_cast<const int4*>(ei + N_EDGES_C + e0);

    int p0 = atomicAdd(&g_count[dst.x], 1);
    int p1 = atomicAdd(&g_count[dst.y], 1);
    int p2 = atomicAdd(&g_count[dst.z], 1);
    int p3 = atomicAdd(&g_count[dst.w], 1);

    if (p0 < CAP) g_bucket[(size_t)dst.x * CAP + p0] = (unsigned)src.x << 8;
    else { int o = atomicAdd(&g_ovf_count, 1); if (o < OVF_CAP) g_ovf_edges[o] = e0; }
    if (p1 < CAP) g_bucket[(size_t)dst.y * CAP + p1] = (unsigned)src.y << 8;
    else { int o = atomicAdd(&g_ovf_count, 1); if (o < OVF_CAP) g_ovf_edges[o] = e0 + 1; }
    if (p2 < CAP) g_bucket[(size_t)dst.z * CAP + p2] = (unsigned)src.z << 8;
    else { int o = atomicAdd(&g_ovf_count, 1); if (o < OVF_CAP) g_ovf_edges[o] = e0 + 2; }
    if (p3 < CAP) g_bucket[(size_t)dst.w * CAP + p3] = (unsigned)src.w << 8;
    else { int o = atomicAdd(&g_ovf_count, 1); if (o < OVF_CAP) g_ovf_edges[o] = e0 + 3; }
}

// -------------------- per-node aggregation body (R12/R13, proven) -----------
__device__ __forceinline__ void aggregate_one_node(
    int node, int lane,
    const unsigned long long* __restrict__ x2u,
    float2* __restrict__ out2,
    const int* __restrict__ ei) {

    const unsigned int* b = &g_bucket[(size_t)node * CAP];
    const char* xb = reinterpret_cast<const char*>(x2u) + lane * 8;

    // concurrent prologue loads (independent)
    uint4 s0 = *reinterpret_cast<const uint4*>(b);
    uint4 s1 = *reinterpret_cast<const uint4*>(b + 4);
    int deg = g_count[node];
    unsigned long long xv = __ldg(&x2u[(size_t)node * 32 + lane]);

    int degc = deg > CAP ? CAP : deg;
    unsigned long long acc = 0ull;

    if (degc > 0) {
        int j = 0;
        while (true) {
            uint4 c0 = s0, c1 = s1;
            int next = j + 8;
            if (next < degc) {
                s0 = *reinterpret_cast<const uint4*>(b + next);
                s1 = *reinterpret_cast<const uint4*>(b + next + 4);
            }
            if (next <= degc) {
                unsigned long long u0 = __ldg((const unsigned long long*)(xb + c0.x));
                unsigned long long u1 = __ldg((const unsigned long long*)(xb + c0.y));
                unsigned long long u2 = __ldg((const unsigned long long*)(xb + c0.z));
                unsigned long long u3 = __ldg((const unsigned long long*)(xb + c0.w));
                unsigned long long u4 = __ldg((const unsigned long long*)(xb + c1.x));
                unsigned long long u5 = __ldg((const unsigned long long*)(xb + c1.y));
                unsigned long long u6 = __ldg((const unsigned long long*)(xb + c1.z));
                unsigned long long u7 = __ldg((const unsigned long long*)(xb + c1.w));
                unsigned long long t01, t23, t45, t67, t03, t47, t07;
                ADD_F32X2(t01, u0, u1);
                ADD_F32X2(t23, u2, u3);
                ADD_F32X2(t45, u4, u5);
                ADD_F32X2(t67, u6, u7);
                ADD_F32X2(t03, t01, t23);
                ADD_F32X2(t47, t45, t67);
                ADD_F32X2(t07, t03, t47);
                ADD_F32X2(acc, acc, t07);
            } else {
                int rem = degc - j;                     // 1..7
                unsigned int offs[8] = { c0.x, c0.y, c0.z, c0.w,
                                         c1.x, c1.y, c1.z, c1.w };
                unsigned long long u[8];
                #pragma unroll
                for (int k = 0; k < 8; k++) {
                    if (k < rem) u[k] = __ldg((const unsigned long long*)(xb + offs[k]));
                    else         u[k] = 0ull;
                }
                unsigned long long t01, t23, t45, t67, t03, t47, t07;
                ADD_F32X2(t01, u[0], u[1]);
                ADD_F32X2(t23, u[2], u[3]);
                ADD_F32X2(t45, u[4], u[5]);
                ADD_F32X2(t67, u[6], u[7]);
                ADD_F32X2(t03, t01, t23);
                ADD_F32X2(t47, t45, t67);
                ADD_F32X2(t07, t03, t47);
                ADD_F32X2(acc, acc, t07);
            }
            j = next;
            if (j >= degc) break;
        }
    }

    float2 accf;
    accf.x = __uint_as_float((unsigned)(acc & 0xffffffffull));
    accf.y = __uint_as_float((unsigned)(acc >> 32));

    int ovf = g_ovf_count;
    if (ovf > 0) {
        if (ovf > OVF_CAP) ovf = OVF_CAP;
        for (int k = 0; k < ovf; k++) {
            int e = g_ovf_edges[k];
            if (__ldg(&ei[N_EDGES_C + e]) == node) {
                int s = __ldg(&ei[e]);
                unsigned long long uu = __ldg(&x2u[(size_t)s * 32 + lane]);
                accf.x += __uint_as_float((unsigned)(uu & 0xffffffffull));
                accf.y += __uint_as_float((unsigned)(uu >> 32));
            }
        }
    }

    float2 xvf;
    xvf.x = __uint_as_float((unsigned)(xv & 0xffffffffull));
    xvf.y = __uint_as_float((unsigned)(xv >> 32));

    float2 o;
    o.x = fmaf(WEIGHT, accf.x, xvf.x);
    o.y = fmaf(WEIGHT, accf.y, xvf.y);
    out2[(size_t)node * 32 + lane] = o;

    if (lane == 0) g_count[node] = 0;   // consume-and-reset
}

// -------------------- 2) aggregate: persistent warps, dynamic tickets -------
__global__ void __launch_bounds__(256, 6)
appr_aggregate_kernel(const unsigned long long* __restrict__ x2u,
                      float2* __restrict__ out2,
                      const int* __restrict__ ei) {
    int lane = threadIdx.x & 31;

    while (true) {
        int base = 0;
        if (lane == 0) base = atomicAdd(&g_ticket, BATCH);
        base = __shfl_sync(0xffffffffu, base, 0);
        if (base >= N_NODES_C) break;
        int end = base + BATCH;
        if (end > N_NODES_C) end = N_NODES_C;
        for (int node = base; node < end; node++) {
            aggregate_one_node(node, lane, x2u, out2, ei);
        }
    }
}

// -------------------- fallback path (unexpected shapes) --------------------
__global__ void appr_copy_kernel(const float4* __restrict__ x4,
                                 float4* __restrict__ out4, long long n_vec) {
    long long i = (long long)blockIdx.x * blockDim.x + threadIdx.x;
    long long stride = (long long)gridDim.x * blockDim.x;
    for (; i < n_vec; i += stride) out4[i] = x4[i];
}

__global__ void appr_scatter_kernel(const float4* __restrict__ x4,
                                    const int* __restrict__ edge_index,
                                    float* __restrict__ out, long long n_edges) {
    long long t = (long long)blockIdx.x * blockDim.x + threadIdx.x;
    long long edge = t >> 4;
    int c = (int)(t & 15);
    if (edge >= n_edges) return;
    int src = __ldg(&edge_index[edge]);
    int dst = __ldg(&edge_index[n_edges + edge]);
    float4 v = __ldg(&x4[(long long)src * D_VEC + c]);
    v.x *= WEIGHT; v.y *= WEIGHT; v.z *= WEIGHT; v.w *= WEIGHT;
    float* p = out + (long long)dst * D_FEAT + c * 4;
    asm volatile("red.global.add.v4.f32 [%0], {%1, %2, %3, %4};"
                 :: "l"(p), "f"(v.x), "f"(v.y), "f"(v.z), "f"(v.w)
                 : "memory");
}

// ---------------------------------------------------------------------------
extern "C" void kernel_launch(void* const* d_in, const int* in_sizes, int n_in,
                              void* d_out, int out_size) {
    const float* x = (const float*)d_in[0];
    const int* edge_index = (const int*)d_in[1];
    float* out = (float*)d_out;

    long long n_x = in_sizes[0];
    long long n_edges = in_sizes[1] / 2;
    long long n_nodes = n_x / D_FEAT;

    if (n_nodes == N_NODES_C && n_edges == N_EDGES_C) {
        // 1) bucket fill (4 edges/thread) + ticket reset
        appr_fill_kernel<<<(N_EDGES_C / 4 + 255) / 256, 256>>>(edge_index);
        // 2) aggregate: persistent warps pulling node batches (BATCH=8)
        appr_aggregate_kernel<<<AGG_BLOCKS, 256>>>(
            (const unsigned long long*)x, (float2*)out, edge_index);
    } else {
        // fallback: copy + RED scatter (touches no persistent state)
        long long n_vec = n_x / 4;
        int blocks = (int)((n_vec + 255) / 256);
        if (blocks > 8192) blocks = 8192;
        appr_copy_kernel<<<blocks, 256>>>((const float4*)x, (float4*)out, n_vec);
        long long total_threads = n_edges * 16;
        appr_scatter_kernel<<<(unsigned)((total_threads + 255) / 256), 256>>>(
            (const float4*)x, edge_index, out, n_edges);
    }
}